// round 1
// baseline (speedup 1.0000x reference)
#include <cuda_runtime.h>
#include <cuda_bf16.h>
#include <cstdint>

// Problem constants
#define BB 32
#define CC 5
#define HH 50
#define SS 20     // seq len for both candidate (s) and clicked (t)
#define EE 300
#define KK 20
#define F4N 75    // EE / 4
#define NCS 100   // CC * SS

// Gaussian kernel constants: mu_k = -0.9f + 0.1f*k (matches ref fp32 arithmetic)
// NC_k = -log2(e) / (2*sigma_k^2);  sigma = 0.1 (k<19), 0.001 (k==19)
#define NC_STD  (-72.134752f)
#define NC_LAST (-721347.52f)

struct Smem {
    float hisT[EE * SS];    // [e][t]  (24000 B)
    float cdd[NCS * EE];    // [cs][e] (120000 B)
    float simbuf[NCS * SS]; // [cs][t] (8000 B)
    float invc[NCS];
    float invh[SS];
    float padh[SS];
    float padc[NCS];
    float wv[KK];
    float cont[256];
};

__device__ float g_partial[BB * HH * CC];

__device__ __forceinline__ float ex2_approx(float x) {
    float r;
    asm("ex2.approx.ftz.f32 %0, %1;" : "=f"(r) : "f"(x));
    return r;
}

__global__ __launch_bounds__(256, 1)
void knrm_main(const int* __restrict__ cand, const int* __restrict__ clk,
               const float* __restrict__ cpad, const float* __restrict__ hpad,
               const float* __restrict__ emb, const float* __restrict__ ltr_w)
{
    extern __shared__ float smraw[];
    Smem* sm = reinterpret_cast<Smem*>(smraw);
    const int tid = threadIdx.x;
    const int b = blockIdx.x / HH;
    const int h = blockIdx.x % HH;

    // ---------------- Gather phase ----------------
    // clicked tile -> transposed hisT[e][t]
    for (int i = tid; i < SS * F4N; i += 256) {
        int t = i / F4N, f = i % F4N;
        int tok = clk[(b * HH + h) * SS + t];
        float4 v = *reinterpret_cast<const float4*>(emb + (size_t)tok * EE + f * 4);
        sm->hisT[(f * 4 + 0) * SS + t] = v.x;
        sm->hisT[(f * 4 + 1) * SS + t] = v.y;
        sm->hisT[(f * 4 + 2) * SS + t] = v.z;
        sm->hisT[(f * 4 + 3) * SS + t] = v.w;
    }
    // candidate tiles (all 5 c), row-major
    for (int i = tid; i < NCS * F4N; i += 256) {
        int r = i / F4N, f = i % F4N;
        int tok = cand[b * NCS + r];
        float4 v = *reinterpret_cast<const float4*>(emb + (size_t)tok * EE + f * 4);
        *reinterpret_cast<float4*>(sm->cdd + r * EE + f * 4) = v;
    }
    if (tid < SS)  sm->padh[tid] = hpad[(b * HH + h) * SS + tid];
    if (tid < KK)  sm->wv[tid]   = ltr_w[h * KK + tid];
    for (int i = tid; i < NCS; i += 256) sm->padc[i] = cpad[b * NCS + i];
    __syncthreads();

    // ---------------- Norms ----------------
    // his norms: 160 threads = (t, octile); octiles are 8-lane aligned within warps 0..4
    if (tid < SS * 8) {
        int t = tid >> 3, p = tid & 7;
        float ss = 0.f;
        for (int e = p; e < EE; e += 8) {
            float v = sm->hisT[e * SS + t];
            ss = fmaf(v, v, ss);
        }
        ss += __shfl_down_sync(0xffffffffu, ss, 4);
        ss += __shfl_down_sync(0xffffffffu, ss, 2);
        ss += __shfl_down_sync(0xffffffffu, ss, 1);
        if (p == 0) sm->invh[t] = 1.0f / fmaxf(sqrtf(ss), 1e-12f);
    }
    // cdd norms: warp per row
    {
        int wid = tid >> 5, lane = tid & 31;
        for (int r = wid; r < NCS; r += 8) {
            float ss = 0.f;
            for (int e = lane; e < EE; e += 32) {
                float v = sm->cdd[r * EE + e];
                ss = fmaf(v, v, ss);
            }
            #pragma unroll
            for (int o = 16; o; o >>= 1) ss += __shfl_down_sync(0xffffffffu, ss, o);
            if (lane == 0) sm->invc[r] = 1.0f / fmaxf(sqrtf(ss), 1e-12f);
        }
    }
    __syncthreads();

    // ---------------- Phase A: sim[cs][t] ----------------
    // thread = (row-pair p in 0..49, e-chunk ec in 0..3); warps 0..6 active (224 thr)
    if (tid < 224) {
        int pair = tid >> 2, ec = tid & 3;
        int pr = pair < 50 ? pair : 49;          // clamp dummies
        int rA = pr * 2, rB = rA + 1;
        int f0 = ec * 19;
        int f1 = (ec == 3) ? F4N : f0 + 19;

        float acc0[SS], acc1[SS];
        #pragma unroll
        for (int t = 0; t < SS; ++t) { acc0[t] = 0.f; acc1[t] = 0.f; }

        const float* cA = sm->cdd + rA * EE;
        const float* cB = sm->cdd + rB * EE;
        for (int f = f0; f < f1; ++f) {
            float4 a4 = *reinterpret_cast<const float4*>(cA + f * 4);
            float4 b4 = *reinterpret_cast<const float4*>(cB + f * 4);
            const float* hb = sm->hisT + f * 4 * SS;
            #pragma unroll
            for (int j = 0; j < 4; ++j) {
                float av = (j == 0) ? a4.x : (j == 1) ? a4.y : (j == 2) ? a4.z : a4.w;
                float bv = (j == 0) ? b4.x : (j == 1) ? b4.y : (j == 2) ? b4.z : b4.w;
                const float4* ht = reinterpret_cast<const float4*>(hb + j * SS);
                #pragma unroll
                for (int q = 0; q < 5; ++q) {
                    float4 h4 = ht[q];
                    acc0[q * 4 + 0] = fmaf(av, h4.x, acc0[q * 4 + 0]);
                    acc0[q * 4 + 1] = fmaf(av, h4.y, acc0[q * 4 + 1]);
                    acc0[q * 4 + 2] = fmaf(av, h4.z, acc0[q * 4 + 2]);
                    acc0[q * 4 + 3] = fmaf(av, h4.w, acc0[q * 4 + 3]);
                    acc1[q * 4 + 0] = fmaf(bv, h4.x, acc1[q * 4 + 0]);
                    acc1[q * 4 + 1] = fmaf(bv, h4.y, acc1[q * 4 + 1]);
                    acc1[q * 4 + 2] = fmaf(bv, h4.z, acc1[q * 4 + 2]);
                    acc1[q * 4 + 3] = fmaf(bv, h4.w, acc1[q * 4 + 3]);
                }
            }
        }
        // reduce over the 4 e-chunk lanes (4-aligned groups within a warp)
        #pragma unroll
        for (int t = 0; t < SS; ++t) {
            acc0[t] += __shfl_down_sync(0xffffffffu, acc0[t], 2);
            acc0[t] += __shfl_down_sync(0xffffffffu, acc0[t], 1);
            acc1[t] += __shfl_down_sync(0xffffffffu, acc1[t], 2);
            acc1[t] += __shfl_down_sync(0xffffffffu, acc1[t], 1);
        }
        if (ec == 0 && pair < 50) {
            float ia = sm->invc[rA], ib = sm->invc[rB];
            #pragma unroll
            for (int t = 0; t < SS; ++t) {
                float ih = sm->invh[t];
                sm->simbuf[rA * SS + t] = acc0[t] * ia * ih;
                sm->simbuf[rB * SS + t] = acc1[t] * ib * ih;
            }
        }
    }
    __syncthreads();

    // ---------------- Phase B: Gaussian pooling + log + weight dot ----------------
    float contrib = 0.0f;
    if (tid < 200) {
        int cs = tid >> 1, kh = tid & 1;
        float ps[10];
        #pragma unroll
        for (int k = 0; k < 10; ++k) ps[k] = 0.f;

        for (int t = 0; t < SS; ++t) {
            float s  = sm->simbuf[cs * SS + t];
            float pt = sm->padh[t];
            #pragma unroll
            for (int k = 0; k < 10; ++k) {
                int kk = kh * 10 + k;            // kh uniform per thread
                float mu = -0.9f + 0.1f * (float)kk;   // match ref fp32 arithmetic
                float nc = (kh == 1 && k == 9) ? NC_LAST : NC_STD;
                float d = s - mu;
                float a = d * d * nc;            // already includes log2(e)
                ps[k] = fmaf(pt, ex2_approx(a), ps[k]);
            }
        }
        float acc = 0.f;
        #pragma unroll
        for (int k = 0; k < 10; ++k) {
            float lp = __logf(fmaxf(ps[k], 1e-10f));
            acc = fmaf(lp, sm->wv[kh * 10 + k], acc);
        }
        contrib = acc * 0.01f * sm->padc[cs];
    }
    sm->cont[tid] = contrib;
    __syncthreads();

    // per-c reduction (40 contiguous slots per c), deterministic
    if (tid < CC) {
        float s = 0.f;
        #pragma unroll 8
        for (int i = 0; i < 40; ++i) s += sm->cont[tid * 40 + i];
        g_partial[(b * HH + h) * CC + tid] = s;
    }
}

__global__ void knrm_final(const float* __restrict__ ltr_b, float* __restrict__ out)
{
    __shared__ float sc[BB * CC];
    int tid = threadIdx.x;
    if (tid < BB * CC) {
        int b = tid / CC, c = tid % CC;
        float s = ltr_b[0];
        for (int hh = 0; hh < HH; ++hh)
            s += g_partial[(b * HH + hh) * CC + c];
        sc[tid] = s;
    }
    __syncthreads();
    if (tid < BB * CC) {
        int b = tid / CC;
        float m = -1e30f;
        #pragma unroll
        for (int c2 = 0; c2 < CC; ++c2) m = fmaxf(m, sc[b * CC + c2]);
        float se = 0.f;
        #pragma unroll
        for (int c2 = 0; c2 < CC; ++c2) se += expf(sc[b * CC + c2] - m);
        out[tid] = sc[tid] - m - logf(se);
    }
}

extern "C" void kernel_launch(void* const* d_in, const int* in_sizes, int n_in,
                              void* d_out, int out_size)
{
    const int*   cand = (const int*)  d_in[0];  // candidate_title  (B,C,S) int32
    const int*   clk  = (const int*)  d_in[1];  // clicked_title    (B,H,S) int32
    const float* cpad = (const float*)d_in[2];  // candidate_title_pad
    const float* hpad = (const float*)d_in[3];  // clicked_title_pad
    const float* emb  = (const float*)d_in[4];  // embedding (V,E)
    const float* w    = (const float*)d_in[5];  // ltr_w (H*K,1)
    const float* bb   = (const float*)d_in[6];  // ltr_b (1,)

    size_t smem = sizeof(Smem);
    cudaFuncSetAttribute(knrm_main, cudaFuncAttributeMaxDynamicSharedMemorySize, (int)smem);

    knrm_main<<<BB * HH, 256, smem>>>(cand, clk, cpad, hpad, emb, w);
    knrm_final<<<1, 192>>>(bb, (float*)d_out);
}